// round 16
// baseline (speedup 1.0000x reference)
#include <cuda_runtime.h>
#include <cuda_fp16.h>
#include <cstdint>
#include <math.h>

#define HW 4096
#define NC 128

// Scratch (static device memory — no allocations allowed)
__device__ float  g_xn[2][NC * HW];        // normalized inputs (residual), fp32
__device__ __half g_qwh[2][3 * NC * NC];   // qkv weights fp16 [384][128]
__device__ __half g_owh[2][NC * NC];       // outproj weights fp16 [128][128]
__device__ __half g_qkv[2][3 * NC * HW];   // qkv projections, fp16 (Q prescaled)
__device__ __half g_po[3][2][NC * HW];     // partial O (unnormalized, fp16) [split][dir]
__device__ float  g_prs[3][8][HW];         // partial rowsums [split][dir*4+h][i]
__device__ float2 g_gnp[2][16][8];         // groupnorm partial sums

// 1/sqrt(128) * log2(e): folded into Q so softmax is a bare ex2
#define QSCALE (0.08838834764831845f * 1.4426950408889634f)

// ---------------------------------------------------------------------------
__device__ __forceinline__ uint32_t s2u(const void* p) {
    uint32_t a;
    asm("{ .reg .u64 t; cvta.to.shared.u64 t, %1; cvt.u32.u64 %0, t; }" : "=r"(a) : "l"(p));
    return a;
}
__device__ __forceinline__ void mma16816(float* c, const uint32_t* a, uint32_t b0, uint32_t b1) {
    asm volatile(
        "mma.sync.aligned.m16n8k16.row.col.f32.f16.f16.f32 "
        "{%0,%1,%2,%3}, {%4,%5,%6,%7}, {%8,%9}, {%0,%1,%2,%3};"
        : "+f"(c[0]), "+f"(c[1]), "+f"(c[2]), "+f"(c[3])
        : "r"(a[0]), "r"(a[1]), "r"(a[2]), "r"(a[3]), "r"(b0), "r"(b1));
}
// fp16-accumulate: C fragment {c0c1},{c2c3} == P A-fragment packing
__device__ __forceinline__ void mma16816h(uint32_t* c, const uint32_t* a, uint32_t b0, uint32_t b1) {
    asm volatile(
        "mma.sync.aligned.m16n8k16.row.col.f16.f16.f16.f16 "
        "{%0,%1}, {%2,%3,%4,%5}, {%6,%7}, {%0,%1};"
        : "+r"(c[0]), "+r"(c[1])
        : "r"(a[0]), "r"(a[1]), "r"(a[2]), "r"(a[3]), "r"(b0), "r"(b1));
}
#define LDSM_T(r, p) \
    asm volatile("ldmatrix.sync.aligned.m8n8.x4.trans.shared.b16 {%0,%1,%2,%3}, [%4];" \
        : "=r"((r)[0]), "=r"((r)[1]), "=r"((r)[2]), "=r"((r)[3]) : "r"(p))
#define LDSM_N(r, p) \
    asm volatile("ldmatrix.sync.aligned.m8n8.x4.shared.b16 {%0,%1,%2,%3}, [%4];" \
        : "=r"((r)[0]), "=r"((r)[1]), "=r"((r)[2]), "=r"((r)[3]) : "r"(p))
#define CP16(dst, src) \
    asm volatile("cp.async.cg.shared.global [%0], [%1], 16;" :: "r"(dst), "l"(src))

// ---------------------------------------------------------------------------
// GroupNorm pass A: partial sums + fp16 weight preconversion.
// grid (16 g, 8 s, 2 t), 256 threads.
// ---------------------------------------------------------------------------
__global__ void gnA_kernel(const float* __restrict__ xA, const float* __restrict__ xB,
                           const float* __restrict__ qwA, const float* __restrict__ qwB,
                           const float* __restrict__ owA, const float* __restrict__ owB) {
    int g = blockIdx.x, s = blockIdx.y, t = blockIdx.z, tid = threadIdx.x;

    // weight conversion: 65536 float2's over 65536 threads
    {
        int flat = ((blockIdx.z * 8 + blockIdx.y) * 16 + blockIdx.x) * 256 + tid;
        const float* src; __half* dst; int i;
        if (flat < 49152) {
            int tt = flat / 24576; i = flat % 24576;
            src = tt ? qwB : qwA; dst = g_qwh[tt];
        } else {
            int r = flat - 49152; int tt = r / 8192; i = r % 8192;
            src = tt ? owB : owA; dst = g_owh[tt];
        }
        float2 f = *(const float2*)&src[i * 2];
        __half2 h = __floats2half2_rn(f.x, f.y);
        *(uint32_t*)&dst[i * 2] = *(uint32_t*)&h;
    }

    const float4* xs = (const float4*)((t ? xB : xA) + g * 32768 + s * 4096);
    float sm = 0.f, sq = 0.f;
    for (int i = tid; i < 1024; i += 256) {
        float4 v = xs[i];
        sm += (v.x + v.y) + (v.z + v.w);
        sq += v.x * v.x + v.y * v.y + v.z * v.z + v.w * v.w;
    }
    __shared__ float s1[256], s2[256];
    s1[tid] = sm; s2[tid] = sq;
    __syncthreads();
    for (int off = 128; off; off >>= 1) {
        if (tid < off) { s1[tid] += s1[tid + off]; s2[tid] += s2[tid + off]; }
        __syncthreads();
    }
    if (tid == 0) g_gnp[t][g][s] = make_float2(s1[0], s2[0]);
}

// ---------------------------------------------------------------------------
// QKV projection (HMMA) + fused GroupNorm apply. W fp16 via cp.async.
// grid (64 hw-tiles of 64, 3 o-tiles of 128, 2 t), 256 threads.
// ---------------------------------------------------------------------------
__global__ void __launch_bounds__(256) qkv_kernel(const float* __restrict__ xA,
                                                  const float* __restrict__ xB,
                                                  const float* __restrict__ gw,
                                                  const float* __restrict__ gb) {
    extern __shared__ char qraw[];
    __half* Ws = (__half*)qraw;              // [128][136]
    __half* Xs = (__half*)(qraw + 34816);    // [128][72]
    __shared__ float scs[128], sbs[128];
    int t = blockIdx.z;
    const float* X = t ? xB : xA;
    __half* Y = g_qkv[t];
    int o0 = blockIdx.y * 128, hw0 = blockIdx.x * 64;
    int tid = threadIdx.x, wid = tid >> 5, L = tid & 31;
    uint32_t wsb = s2u(Ws), xsb = s2u(Xs);

    // W via cp.async (fp16 preconverted)
#pragma unroll
    for (int u = 0; u < 8; u++) {
        int idx = tid + 256 * u;         // 2048 chunks
        int row = idx >> 4, c8 = (idx & 15) * 8;
        CP16(wsb + (row * 136 + c8) * 2, g_qwh[t] + (o0 + row) * 128 + c8);
    }
    asm volatile("cp.async.commit_group;" ::: "memory");

    // per-channel GN scale/bias from gnA partials
    if (tid < 128) {
        int c = tid, g = c >> 3;
        float sm = 0.f, sq = 0.f;
#pragma unroll
        for (int p = 0; p < 8; p++) {
            float2 v = g_gnp[t][g][p];
            sm += v.x; sq += v.y;
        }
        float mu  = sm * (1.f / 32768.f);
        float var = sq * (1.f / 32768.f) - mu * mu;
        float inv = rsqrtf(var + 1e-5f);
        float sc = inv * gw[c];
        scs[c] = sc;
        sbs[c] = gb[c] - mu * sc;
    }
    __syncthreads();

    // X tile [128 ch][64 hw]: load, normalize, cvt; write residual (by==0)
#pragma unroll
    for (int u = 0; u < 8; u++) {
        int idx = tid + 256 * u;         // 2048 chunks of 4 floats
        int row = idx >> 4, c4 = (idx & 15) * 4;
        float sc = scs[row], bb = sbs[row];
        float4 f = *(const float4*)&X[row * HW + hw0 + c4];
        f.x = f.x * sc + bb; f.y = f.y * sc + bb;
        f.z = f.z * sc + bb; f.w = f.w * sc + bb;
        if (blockIdx.y == 0)
            *(float4*)&g_xn[t][row * HW + hw0 + c4] = f;
        __half2 h0 = __floats2half2_rn(f.x, f.y);
        __half2 h1 = __floats2half2_rn(f.z, f.w);
        *(uint2*)&Xs[row * 72 + c4] = make_uint2(*(uint32_t*)&h0, *(uint32_t*)&h1);
    }
    asm volatile("cp.async.wait_group 0;" ::: "memory");
    __syncthreads();

    int wr = wid & 3, wc = wid >> 2;     // 8 warps: 4 row-groups x 2 col-groups
    uint32_t abase = wsb + ((32 * wr + (L & 15)) * 136 + ((L >> 4) & 1) * 8) * 2;
    uint32_t bbase = xsb + (((L & 7) + ((L >> 3) & 1) * 8) * 72 + 32 * wc + ((L >> 4) & 1) * 8) * 2;
    float acc[2][4][4] = {};
#pragma unroll
    for (int kk = 0; kk < 8; kk++) {
        uint32_t a0[4], a1[4];
        LDSM_N(a0, abase + (16 * kk) * 2);
        LDSM_N(a1, abase + (16 * 136 + 16 * kk) * 2);
        uint32_t bfr[2][4];
#pragma unroll
        for (int nn = 0; nn < 2; nn++)
            LDSM_T(bfr[nn], bbase + (16 * kk * 72 + 16 * nn) * 2);
#pragma unroll
        for (int nn = 0; nn < 2; nn++) {
            mma16816(acc[0][2 * nn],     a0, bfr[nn][0], bfr[nn][1]);
            mma16816(acc[0][2 * nn + 1], a0, bfr[nn][2], bfr[nn][3]);
            mma16816(acc[1][2 * nn],     a1, bfr[nn][0], bfr[nn][1]);
            mma16816(acc[1][2 * nn + 1], a1, bfr[nn][2], bfr[nn][3]);
        }
    }
#pragma unroll
    for (int mi = 0; mi < 2; mi++) {
        int row = o0 + 32 * wr + 16 * mi + (L >> 2);
        int row8 = row + 8;
        float s0 = ((row % 96) < 32) ? QSCALE : 1.f;
        float s1 = ((row8 % 96) < 32) ? QSCALE : 1.f;
#pragma unroll
        for (int nb = 0; nb < 4; nb++) {
            int col = hw0 + 32 * wc + 8 * nb + 2 * (L & 3);
            __half2 p0 = __floats2half2_rn(acc[mi][nb][0] * s0, acc[mi][nb][1] * s0);
            __half2 p1 = __floats2half2_rn(acc[mi][nb][2] * s1, acc[mi][nb][3] * s1);
            *(__half2*)&Y[row * HW + col] = p0;
            *(__half2*)&Y[row8 * HW + col] = p1;
        }
    }
}

// ---------------------------------------------------------------------------
// Cross-attention (HMMA), SPLIT-KV x3. BM=128, 128 threads = 4 warps x 32 rows.
// grid (32 i-tiles, 8 = dir*4+head, 3 splits): stages 11/11/10 of 128 cols.
// Per-sub processing keeps live regs low; __launch_bounds__(128,5).
// Rowsum via ones-MMA (measured better than HADD2 tree at this occupancy).
// Partials written fp16 (magnitude <= ~200, fp16-safe; halves traffic).
// NOTE: __syncthreads after the stage loop is LOAD-BEARING — the epilogue
// overlays KV buffer 0, which the final stage reads when nst is odd.
// ---------------------------------------------------------------------------
#define QS_SZ 8704            // Q [32][136] halves
#define BUF_SZ 17408          // K[32][136] + V[32][136]

__device__ __forceinline__ void attn_cp(const __half* Kb, const __half* Vb, int j0,
                                        uint32_t bufb, int tid) {
#pragma unroll
    for (int r = 0; r < 8; r++) {
        int idx = tid + 128 * r;            // 1024 chunks of 16B
        int mat = idx >> 9, wi = idx & 511;
        int dd = wi >> 4, c = wi & 15;
        const __half* src = (mat ? Vb : Kb) + dd * HW + j0 + c * 8;
        CP16(bufb + mat * 8704 + dd * 272 + c * 16, src);
    }
    asm volatile("cp.async.commit_group;" ::: "memory");
}

__global__ void __launch_bounds__(128, 5) attn_kernel() {
    extern __shared__ char araw[];
    const uint32_t qsb = s2u(araw);
    const uint32_t bufb0 = qsb + QS_SZ;

    const int tid = threadIdx.x, wid = tid >> 5, L = tid & 31;
    const int ib = blockIdx.x, hd = blockIdx.y, sp = blockIdx.z;
    const int dir = hd >> 2, h = hd & 3;
    const __half* Qb = g_qkv[dir ^ 1] + (h * 96 + 0) * HW;   // Q from the other stream
    const __half* Kb = g_qkv[dir]     + (h * 96 + 32) * HW;
    const __half* Vb = g_qkv[dir]     + (h * 96 + 64) * HW;
    const int i0 = ib * 128;
    const int jbase = sp * 1408;
    const int nst = (sp < 2) ? 11 : 10;

    attn_cp(Kb, Vb, jbase, bufb0, tid);

    // stage Q tile [32 d][128 i]
    __half* Qs = (__half*)araw;
#pragma unroll
    for (int r = 0; r < 4; r++) {
        int idx = tid + 128 * r;          // 512 chunks
        int dd = idx >> 4, c = idx & 15;
        *(uint4*)&Qs[dd * 136 + c * 8] = *(const uint4*)(Qb + dd * HW + i0 + c * 8);
    }
    __syncthreads();

    // hoist Q A-fragments: warp rows 32*wid + 16*m
    uint32_t qa[2][2][4];
#pragma unroll
    for (int m = 0; m < 2; m++)
#pragma unroll
        for (int s = 0; s < 2; s++) {
            int d_ = 16 * s + (L & 7) + ((L >> 4) & 1) * 8;
            int ii = 32 * wid + 16 * m + ((L >> 3) & 1) * 8;
            LDSM_T(qa[m][s], qsb + (d_ * 136 + ii) * 2);
        }

    const uint32_t klane = ((L & 7) + ((L >> 3) & 1) * 8) * 272 + ((L >> 4) & 1) * 16;
    const uint32_t vlane = ((L & 7) + ((L >> 4) & 1) * 8) * 272 + ((L >> 3) & 1) * 16;
    const uint32_t ONES = (L < 4) ? 0x3C003C00u : 0u;   // ones col (n=0) B-fragment

    float oacc[2][4][4] = {};
    float racc[2][4] = {};

    for (int st = 0; st < nst; st++) {
        asm volatile("cp.async.wait_group 0;" ::: "memory");
        __syncthreads();   // cp(st) visible to all warps; buffer (st+1)&1 free
        if (st < nst - 1)
            attn_cp(Kb, Vb, jbase + (st + 1) * 128, bufb0 + ((st + 1) & 1) * BUF_SZ, tid);

        const uint32_t bb = bufb0 + (st & 1) * BUF_SZ;
        const uint32_t kb = bb + klane;
        const uint32_t vb = bb + 8704 + vlane;

#pragma unroll
        for (int sub = 0; sub < 2; sub++) {
            // ---- S-MMAs for this 64-col sub (fp16 accum; C frag == P A-frag) ----
            uint32_t sh[2][8][2] = {};   // [m][nb][half]
#pragma unroll
            for (int s = 0; s < 2; s++)
#pragma unroll
                for (int p = 0; p < 4; p++) {
                    uint32_t kf[4];
                    LDSM_T(kf, kb + (16 * s) * 272 + sub * 128 + p * 32);
                    mma16816h(sh[0][2 * p],     qa[0][s], kf[0], kf[1]);
                    mma16816h(sh[0][2 * p + 1], qa[0][s], kf[2], kf[3]);
                    mma16816h(sh[1][2 * p],     qa[1][s], kf[0], kf[1]);
                    mma16816h(sh[1][2 * p + 1], qa[1][s], kf[2], kf[3]);
                }

            // ---- exp2 in place ----
            {
                uint32_t* shp = &sh[0][0][0];
#pragma unroll
                for (int u = 0; u < 32; u++)
                    asm("ex2.approx.f16x2 %0, %0;" : "+r"(shp[u]));
            }

            // ---- O-MMAs + rowsum MMA ----
#pragma unroll
            for (int k2 = 0; k2 < 4; k2++) {
                uint32_t v0[4], v1[4];
                LDSM_N(v0, vb + sub * 128 + k2 * 32);
                LDSM_N(v1, vb + 16 * 272 + sub * 128 + k2 * 32);
#pragma unroll
                for (int m = 0; m < 2; m++) {
                    uint32_t pa[4] = {sh[m][2 * k2][0], sh[m][2 * k2][1],
                                      sh[m][2 * k2 + 1][0], sh[m][2 * k2 + 1][1]};
                    mma16816(oacc[m][0], pa, v0[0], v0[1]);
                    mma16816(oacc[m][1], pa, v0[2], v0[3]);
                    mma16816(oacc[m][2], pa, v1[0], v1[1]);
                    mma16816(oacc[m][3], pa, v1[2], v1[3]);
                    mma16816(racc[m],    pa, ONES, ONES);
                }
            }
        }
    }

    // LOAD-BEARING: all warps must finish reading the KV ring before the
    // epilogue overlays buffer 0 (final stage reads buffer 0 when nst is odd).
    __syncthreads();

    // partial rowsums (col0 lives in lanes L%4==0: c0 -> row r, c2 -> row r+8)
    if ((L & 3) == 0) {
#pragma unroll
        for (int m = 0; m < 2; m++) {
            int r = 32 * wid + 16 * m + (L >> 2);
            g_prs[sp][hd][i0 + r]     = racc[m][0];
            g_prs[sp][hd][i0 + r + 8] = racc[m][2];
        }
    }

    // stage partial O (fp16, unnormalized) into smem [d][i], coalesced store
    __half* Osm = (__half*)(araw + QS_SZ);   // 32*136 halves = 8704B
#pragma unroll
    for (int m = 0; m < 2; m++)
#pragma unroll
        for (int nb = 0; nb < 4; nb++) {
            int d_ = 8 * nb + 2 * (L & 3);
            int r = 32 * wid + 16 * m + (L >> 2);
            Osm[d_ * 136 + r]           = __float2half(oacc[m][nb][0]);
            Osm[(d_ + 1) * 136 + r]     = __float2half(oacc[m][nb][1]);
            Osm[d_ * 136 + r + 8]       = __float2half(oacc[m][nb][2]);
            Osm[(d_ + 1) * 136 + r + 8] = __float2half(oacc[m][nb][3]);
        }
    __syncthreads();
    __half* Pd = g_po[sp][dir];
#pragma unroll
    for (int u = 0; u < 4; u++) {
        int idx = tid + 128 * u;         // 512 = 32 rows x 16 chunks of 8
        int dd = idx >> 4, c = idx & 15;
        uint4 v = *(uint4*)&Osm[dd * 136 + c * 8];
        *(uint4*)&Pd[(h * 32 + dd) * HW + i0 + c * 8] = v;
    }
}

// ---------------------------------------------------------------------------
// Out projection (HMMA) + FUSED 3-way split-KV combine + bias + residual.
// grid (64 hw-tiles of 64, 2 t), 512 threads — ONE block per hw-tile does all
// 128 output rows; fp16 partials read exactly once (6MB total).
// ---------------------------------------------------------------------------
__global__ void __launch_bounds__(512) outproj_kernel(const float* __restrict__ bA,
                                                      const float* __restrict__ bB,
                                                      float* __restrict__ out) {
    extern __shared__ char oraw[];
    uint32_t wsb = s2u(oraw);                       // W [128][136] halves (34816B)
    uint32_t osb = wsb + 34816;                     // O [128][72] halves  (18432B)
    uint32_t rsb = osb + 18432;                     // res [128][64] f32   (32768B)
    __half* Os = (__half*)(oraw + 34816);
    float* Rs = (float*)(oraw + 34816 + 18432);
    __shared__ float bs[128];
    __shared__ float invs[4][64];
    int t = blockIdx.y;
    const float* bias = t ? bB : bA;
    const float* res = g_xn[t];
    float* Y = out + t * (NC * HW);
    int hw0 = blockIdx.x * 64;
    int tid = threadIdx.x, wid = tid >> 5, L = tid & 31;

#pragma unroll
    for (int u = 0; u < 4; u++) {
        int idx = tid + 512 * u;         // 2048 chunks: W 128 rows x 128 cols
        int row = idx >> 4, c8 = (idx & 15) * 8;
        CP16(wsb + (row * 136 + c8) * 2, g_owh[t] + row * 128 + c8);
    }
#pragma unroll
    for (int u = 0; u < 4; u++) {
        int idx = tid + 512 * u;         // 2048 chunks: res 128x64 f32
        int row = idx >> 4, c4 = (idx & 15) * 4;
        CP16(rsb + (row * 64 + c4) * 4, res + row * HW + hw0 + c4);
    }
    asm volatile("cp.async.commit_group;" ::: "memory");
    if (tid < 128) bs[tid] = bias[tid];

    // inverse combined rowsums: invs[h][c] = 1/(rs0+rs1+rs2)
    if (tid < 256) {
        int h = tid >> 6, c = tid & 63;
        float s = g_prs[0][t * 4 + h][hw0 + c] + g_prs[1][t * 4 + h][hw0 + c]
                + g_prs[2][t * 4 + h][hw0 + c];
        invs[h][c] = 1.f / s;
    }
    __syncthreads();

    // fused combine: O[128][64] = (p0+p1+p2)*inv -> fp16 smem (pitch 72)
    const __half* P0 = g_po[0][t];
    const __half* P1 = g_po[1][t];
    const __half* P2 = g_po[2][t];
#pragma unroll
    for (int u = 0; u < 4; u++) {
        int idx = tid + 512 * u;         // 2048 groups of 4 halves
        int row = idx >> 4, c4 = (idx & 15) * 4;
        int off = row * HW + hw0 + c4;
        uint2 a = *(const uint2*)&P0[off];
        uint2 b = *(const uint2*)&P1[off];
        uint2 d = *(const uint2*)&P2[off];
        __half2 slo = __hadd2(__hadd2(*(__half2*)&a.x, *(__half2*)&b.x), *(__half2*)&d.x);
        __half2 shi = __hadd2(__hadd2(*(__half2*)&a.y, *(__half2*)&b.y), *(__half2*)&d.y);
        float4 iv = *(const float4*)&invs[row >> 5][c4];
        float2 flo = __half22float2(slo);
        float2 fhi = __half22float2(shi);
        __half2 h0 = __floats2half2_rn(flo.x * iv.x, flo.y * iv.y);
        __half2 h1 = __floats2half2_rn(fhi.x * iv.z, fhi.y * iv.w);
        *(uint2*)&Os[row * 72 + c4] = make_uint2(*(uint32_t*)&h0, *(uint32_t*)&h1);
    }
    asm volatile("cp.async.wait_group 0;" ::: "memory");
    __syncthreads();

    int wr = wid & 7, wc = wid >> 3;     // 16 warps: 8 row-groups(16) x 2 col-groups(32)
    uint32_t abase = wsb + ((16 * wr + (L & 15)) * 136 + ((L >> 4) & 1) * 8) * 2;
    uint32_t bbase = osb + (((L & 7) + ((L >> 3) & 1) * 8) * 72 + 32 * wc + ((L >> 4) & 1) * 8) * 2;
    float acc[4][4] = {};
#pragma unroll
    for (int kk = 0; kk < 8; kk++) {
        uint32_t a0[4];
        LDSM_N(a0, abase + (16 * kk) * 2);
        uint32_t bfr[2][4];
#pragma unroll
        for (int nn = 0; nn < 2; nn++)
            LDSM_T(bfr[nn], bbase + (16 * kk * 72 + 16 * nn) * 2);
#pragma unroll
        for (int nn = 0; nn < 2; nn++) {
            mma16816(acc[2 * nn],     a0, bfr[nn][0], bfr[nn][1]);
            mma16816(acc[2 * nn + 1], a0, bfr[nn][2], bfr[nn][3]);
        }
    }
    {
        int rl = 16 * wr + (L >> 2);
#pragma unroll
        for (int nb = 0; nb < 4; nb++) {
            int cl = 32 * wc + 8 * nb + 2 * (L & 3);
            float2 r0 = *(float2*)&Rs[rl * 64 + cl];
            float2 v0;
            v0.x = acc[nb][0] + bs[rl] + r0.x;
            v0.y = acc[nb][1] + bs[rl] + r0.y;
            *(float2*)&Y[rl * HW + hw0 + cl] = v0;
            float2 r1 = *(float2*)&Rs[(rl + 8) * 64 + cl];
            float2 v1;
            v1.x = acc[nb][2] + bs[rl + 8] + r1.x;
            v1.y = acc[nb][3] + bs[rl + 8] + r1.y;
            *(float2*)&Y[(rl + 8) * HW + hw0 + cl] = v1;
        }
    }
}

// ---------------------------------------------------------------------------
extern "C" void kernel_launch(void* const* d_in, const int* in_sizes, int n_in,
                              void* d_out, int out_size) {
    const float* xA    = (const float*)d_in[0];
    const float* xB    = (const float*)d_in[1];
    const float* gnw   = (const float*)d_in[2];
    const float* gnb   = (const float*)d_in[3];
    const float* qkvAw = (const float*)d_in[4];
    const float* outAw = (const float*)d_in[5];
    const float* outAb = (const float*)d_in[6];
    const float* qkvBw = (const float*)d_in[7];
    const float* outBw = (const float*)d_in[8];
    const float* outBb = (const float*)d_in[9];
    float* out = (float*)d_out;

    const int QKV_SMEM  = 34816 + 18432;            // 53248
    const int ATTN_SMEM = QS_SZ + 2 * BUF_SZ;       // 43520
    const int OUT_SMEM  = 34816 + 18432 + 32768;    // 86016
    cudaFuncSetAttribute(qkv_kernel, cudaFuncAttributeMaxDynamicSharedMemorySize, QKV_SMEM);
    cudaFuncSetAttribute(attn_kernel, cudaFuncAttributeMaxDynamicSharedMemorySize, ATTN_SMEM);
    cudaFuncSetAttribute(outproj_kernel, cudaFuncAttributeMaxDynamicSharedMemorySize, OUT_SMEM);

    gnA_kernel<<<dim3(16, 8, 2), 256>>>(xA, xB, qkvAw, qkvBw, outAw, outBw);
    qkv_kernel<<<dim3(64, 3, 2), 256, QKV_SMEM>>>(xA, xB, gnw, gnb);
    attn_kernel<<<dim3(32, 8, 3), 128, ATTN_SMEM>>>();
    outproj_kernel<<<dim3(64, 2), 512, OUT_SMEM>>>(outAb, outBb, out);
}

// round 17
// speedup vs baseline: 1.0052x; 1.0052x over previous
#include <cuda_runtime.h>
#include <cuda_fp16.h>
#include <cstdint>
#include <math.h>

#define HW 4096
#define NC 128

// Scratch (static device memory — no allocations allowed)
__device__ float  g_xn[2][NC * HW];        // normalized inputs (residual), fp32
__device__ __half g_qwh[2][3 * NC * NC];   // qkv weights fp16 [384][128]
__device__ __half g_owh[2][NC * NC];       // outproj weights fp16 [128][128]
__device__ __half g_qkv[2][3 * NC * HW];   // qkv projections, fp16 (Q prescaled)
__device__ __half g_po[3][2][NC * HW];     // partial O (unnormalized, fp16) [split][dir]
__device__ float  g_prs[3][8][HW];         // partial rowsums [split][dir*4+h][i]
__device__ float2 g_gnp[2][16][8];         // groupnorm partial sums

// 1/sqrt(128) * log2(e): folded into Q so softmax is a bare ex2
#define QSCALE (0.08838834764831845f * 1.4426950408889634f)

// ---------------------------------------------------------------------------
__device__ __forceinline__ uint32_t s2u(const void* p) {
    uint32_t a;
    asm("{ .reg .u64 t; cvta.to.shared.u64 t, %1; cvt.u32.u64 %0, t; }" : "=r"(a) : "l"(p));
    return a;
}
__device__ __forceinline__ void mma16816(float* c, const uint32_t* a, uint32_t b0, uint32_t b1) {
    asm volatile(
        "mma.sync.aligned.m16n8k16.row.col.f32.f16.f16.f32 "
        "{%0,%1,%2,%3}, {%4,%5,%6,%7}, {%8,%9}, {%0,%1,%2,%3};"
        : "+f"(c[0]), "+f"(c[1]), "+f"(c[2]), "+f"(c[3])
        : "r"(a[0]), "r"(a[1]), "r"(a[2]), "r"(a[3]), "r"(b0), "r"(b1));
}
// fp16-accumulate: C fragment {c0c1},{c2c3} == P A-fragment packing
__device__ __forceinline__ void mma16816h(uint32_t* c, const uint32_t* a, uint32_t b0, uint32_t b1) {
    asm volatile(
        "mma.sync.aligned.m16n8k16.row.col.f16.f16.f16.f16 "
        "{%0,%1}, {%2,%3,%4,%5}, {%6,%7}, {%0,%1};"
        : "+r"(c[0]), "+r"(c[1])
        : "r"(a[0]), "r"(a[1]), "r"(a[2]), "r"(a[3]), "r"(b0), "r"(b1));
}
#define LDSM_T(r, p) \
    asm volatile("ldmatrix.sync.aligned.m8n8.x4.trans.shared.b16 {%0,%1,%2,%3}, [%4];" \
        : "=r"((r)[0]), "=r"((r)[1]), "=r"((r)[2]), "=r"((r)[3]) : "r"(p))
#define LDSM_N(r, p) \
    asm volatile("ldmatrix.sync.aligned.m8n8.x4.shared.b16 {%0,%1,%2,%3}, [%4];" \
        : "=r"((r)[0]), "=r"((r)[1]), "=r"((r)[2]), "=r"((r)[3]) : "r"(p))
#define CP16(dst, src) \
    asm volatile("cp.async.cg.shared.global [%0], [%1], 16;" :: "r"(dst), "l"(src))

// ---------------------------------------------------------------------------
// GroupNorm pass A: partial sums + fp16 weight preconversion.
// grid (16 g, 8 s, 2 t), 256 threads.
// ---------------------------------------------------------------------------
__global__ void gnA_kernel(const float* __restrict__ xA, const float* __restrict__ xB,
                           const float* __restrict__ qwA, const float* __restrict__ qwB,
                           const float* __restrict__ owA, const float* __restrict__ owB) {
    int g = blockIdx.x, s = blockIdx.y, t = blockIdx.z, tid = threadIdx.x;

    // weight conversion: 65536 float2's over 65536 threads
    {
        int flat = ((blockIdx.z * 8 + blockIdx.y) * 16 + blockIdx.x) * 256 + tid;
        const float* src; __half* dst; int i;
        if (flat < 49152) {
            int tt = flat / 24576; i = flat % 24576;
            src = tt ? qwB : qwA; dst = g_qwh[tt];
        } else {
            int r = flat - 49152; int tt = r / 8192; i = r % 8192;
            src = tt ? owB : owA; dst = g_owh[tt];
        }
        float2 f = *(const float2*)&src[i * 2];
        __half2 h = __floats2half2_rn(f.x, f.y);
        *(uint32_t*)&dst[i * 2] = *(uint32_t*)&h;
    }

    const float4* xs = (const float4*)((t ? xB : xA) + g * 32768 + s * 4096);
    float sm = 0.f, sq = 0.f;
    for (int i = tid; i < 1024; i += 256) {
        float4 v = xs[i];
        sm += (v.x + v.y) + (v.z + v.w);
        sq += v.x * v.x + v.y * v.y + v.z * v.z + v.w * v.w;
    }
    __shared__ float s1[256], s2[256];
    s1[tid] = sm; s2[tid] = sq;
    __syncthreads();
    for (int off = 128; off; off >>= 1) {
        if (tid < off) { s1[tid] += s1[tid + off]; s2[tid] += s2[tid + off]; }
        __syncthreads();
    }
    if (tid == 0) g_gnp[t][g][s] = make_float2(s1[0], s2[0]);
}

// ---------------------------------------------------------------------------
// QKV projection (HMMA) + fused GroupNorm apply. W fp16 via cp.async.
// grid (64 hw-tiles of 64, 3 o-tiles of 128, 2 t), 256 threads.
// ---------------------------------------------------------------------------
__global__ void __launch_bounds__(256) qkv_kernel(const float* __restrict__ xA,
                                                  const float* __restrict__ xB,
                                                  const float* __restrict__ gw,
                                                  const float* __restrict__ gb) {
    extern __shared__ char qraw[];
    __half* Ws = (__half*)qraw;              // [128][136]
    __half* Xs = (__half*)(qraw + 34816);    // [128][72]
    __shared__ float scs[128], sbs[128];
    int t = blockIdx.z;
    const float* X = t ? xB : xA;
    __half* Y = g_qkv[t];
    int o0 = blockIdx.y * 128, hw0 = blockIdx.x * 64;
    int tid = threadIdx.x, wid = tid >> 5, L = tid & 31;
    uint32_t wsb = s2u(Ws), xsb = s2u(Xs);

    // W via cp.async (fp16 preconverted)
#pragma unroll
    for (int u = 0; u < 8; u++) {
        int idx = tid + 256 * u;         // 2048 chunks
        int row = idx >> 4, c8 = (idx & 15) * 8;
        CP16(wsb + (row * 136 + c8) * 2, g_qwh[t] + (o0 + row) * 128 + c8);
    }
    asm volatile("cp.async.commit_group;" ::: "memory");

    // per-channel GN scale/bias from gnA partials
    if (tid < 128) {
        int c = tid, g = c >> 3;
        float sm = 0.f, sq = 0.f;
#pragma unroll
        for (int p = 0; p < 8; p++) {
            float2 v = g_gnp[t][g][p];
            sm += v.x; sq += v.y;
        }
        float mu  = sm * (1.f / 32768.f);
        float var = sq * (1.f / 32768.f) - mu * mu;
        float inv = rsqrtf(var + 1e-5f);
        float sc = inv * gw[c];
        scs[c] = sc;
        sbs[c] = gb[c] - mu * sc;
    }
    __syncthreads();

    // X tile [128 ch][64 hw]: load, normalize, cvt; write residual (by==0)
#pragma unroll
    for (int u = 0; u < 8; u++) {
        int idx = tid + 256 * u;         // 2048 chunks of 4 floats
        int row = idx >> 4, c4 = (idx & 15) * 4;
        float sc = scs[row], bb = sbs[row];
        float4 f = *(const float4*)&X[row * HW + hw0 + c4];
        f.x = f.x * sc + bb; f.y = f.y * sc + bb;
        f.z = f.z * sc + bb; f.w = f.w * sc + bb;
        if (blockIdx.y == 0)
            *(float4*)&g_xn[t][row * HW + hw0 + c4] = f;
        __half2 h0 = __floats2half2_rn(f.x, f.y);
        __half2 h1 = __floats2half2_rn(f.z, f.w);
        *(uint2*)&Xs[row * 72 + c4] = make_uint2(*(uint32_t*)&h0, *(uint32_t*)&h1);
    }
    asm volatile("cp.async.wait_group 0;" ::: "memory");
    __syncthreads();

    int wr = wid & 3, wc = wid >> 2;     // 8 warps: 4 row-groups x 2 col-groups
    uint32_t abase = wsb + ((32 * wr + (L & 15)) * 136 + ((L >> 4) & 1) * 8) * 2;
    uint32_t bbase = xsb + (((L & 7) + ((L >> 3) & 1) * 8) * 72 + 32 * wc + ((L >> 4) & 1) * 8) * 2;
    float acc[2][4][4] = {};
#pragma unroll
    for (int kk = 0; kk < 8; kk++) {
        uint32_t a0[4], a1[4];
        LDSM_N(a0, abase + (16 * kk) * 2);
        LDSM_N(a1, abase + (16 * 136 + 16 * kk) * 2);
        uint32_t bfr[2][4];
#pragma unroll
        for (int nn = 0; nn < 2; nn++)
            LDSM_T(bfr[nn], bbase + (16 * kk * 72 + 16 * nn) * 2);
#pragma unroll
        for (int nn = 0; nn < 2; nn++) {
            mma16816(acc[0][2 * nn],     a0, bfr[nn][0], bfr[nn][1]);
            mma16816(acc[0][2 * nn + 1], a0, bfr[nn][2], bfr[nn][3]);
            mma16816(acc[1][2 * nn],     a1, bfr[nn][0], bfr[nn][1]);
            mma16816(acc[1][2 * nn + 1], a1, bfr[nn][2], bfr[nn][3]);
        }
    }
#pragma unroll
    for (int mi = 0; mi < 2; mi++) {
        int row = o0 + 32 * wr + 16 * mi + (L >> 2);
        int row8 = row + 8;
        float s0 = ((row % 96) < 32) ? QSCALE : 1.f;
        float s1 = ((row8 % 96) < 32) ? QSCALE : 1.f;
#pragma unroll
        for (int nb = 0; nb < 4; nb++) {
            int col = hw0 + 32 * wc + 8 * nb + 2 * (L & 3);
            __half2 p0 = __floats2half2_rn(acc[mi][nb][0] * s0, acc[mi][nb][1] * s0);
            __half2 p1 = __floats2half2_rn(acc[mi][nb][2] * s1, acc[mi][nb][3] * s1);
            *(__half2*)&Y[row * HW + col] = p0;
            *(__half2*)&Y[row8 * HW + col] = p1;
        }
    }
}

// ---------------------------------------------------------------------------
// Cross-attention (HMMA), SPLIT-KV x3. BM=128, 128 threads = 4 warps x 32 rows.
// grid (32 i-tiles, 8 = dir*4+head, 3 splits): stages 11/11/10 of 128 cols.
// O accumulates in FP16 (testing half-rate f32-accum HMMA hypothesis);
// rowsum stays on f32-accum ones-MMA (accumulator ~1600, fp16 too coarse).
// NOTE: __syncthreads after the stage loop is LOAD-BEARING — the epilogue
// overlays KV buffer 0, which the final stage reads when nst is odd.
// ---------------------------------------------------------------------------
#define QS_SZ 8704            // Q [32][136] halves
#define BUF_SZ 17408          // K[32][136] + V[32][136]

__device__ __forceinline__ void attn_cp(const __half* Kb, const __half* Vb, int j0,
                                        uint32_t bufb, int tid) {
#pragma unroll
    for (int r = 0; r < 8; r++) {
        int idx = tid + 128 * r;            // 1024 chunks of 16B
        int mat = idx >> 9, wi = idx & 511;
        int dd = wi >> 4, c = wi & 15;
        const __half* src = (mat ? Vb : Kb) + dd * HW + j0 + c * 8;
        CP16(bufb + mat * 8704 + dd * 272 + c * 16, src);
    }
    asm volatile("cp.async.commit_group;" ::: "memory");
}

__global__ void __launch_bounds__(128, 5) attn_kernel() {
    extern __shared__ char araw[];
    const uint32_t qsb = s2u(araw);
    const uint32_t bufb0 = qsb + QS_SZ;

    const int tid = threadIdx.x, wid = tid >> 5, L = tid & 31;
    const int ib = blockIdx.x, hd = blockIdx.y, sp = blockIdx.z;
    const int dir = hd >> 2, h = hd & 3;
    const __half* Qb = g_qkv[dir ^ 1] + (h * 96 + 0) * HW;   // Q from the other stream
    const __half* Kb = g_qkv[dir]     + (h * 96 + 32) * HW;
    const __half* Vb = g_qkv[dir]     + (h * 96 + 64) * HW;
    const int i0 = ib * 128;
    const int jbase = sp * 1408;
    const int nst = (sp < 2) ? 11 : 10;

    attn_cp(Kb, Vb, jbase, bufb0, tid);

    // stage Q tile [32 d][128 i]
    __half* Qs = (__half*)araw;
#pragma unroll
    for (int r = 0; r < 4; r++) {
        int idx = tid + 128 * r;          // 512 chunks
        int dd = idx >> 4, c = idx & 15;
        *(uint4*)&Qs[dd * 136 + c * 8] = *(const uint4*)(Qb + dd * HW + i0 + c * 8);
    }
    __syncthreads();

    // hoist Q A-fragments: warp rows 32*wid + 16*m
    uint32_t qa[2][2][4];
#pragma unroll
    for (int m = 0; m < 2; m++)
#pragma unroll
        for (int s = 0; s < 2; s++) {
            int d_ = 16 * s + (L & 7) + ((L >> 4) & 1) * 8;
            int ii = 32 * wid + 16 * m + ((L >> 3) & 1) * 8;
            LDSM_T(qa[m][s], qsb + (d_ * 136 + ii) * 2);
        }

    const uint32_t klane = ((L & 7) + ((L >> 3) & 1) * 8) * 272 + ((L >> 4) & 1) * 16;
    const uint32_t vlane = ((L & 7) + ((L >> 4) & 1) * 8) * 272 + ((L >> 3) & 1) * 16;
    const uint32_t ONES = (L < 4) ? 0x3C003C00u : 0u;   // ones col (n=0) B-fragment

    uint32_t oacc[2][4][2] = {};   // fp16 O accumulators [m][nb][reg]
    float racc[2][4] = {};         // f32 rowsum (ones-MMA)

    for (int st = 0; st < nst; st++) {
        asm volatile("cp.async.wait_group 0;" ::: "memory");
        __syncthreads();   // cp(st) visible to all warps; buffer (st+1)&1 free
        if (st < nst - 1)
            attn_cp(Kb, Vb, jbase + (st + 1) * 128, bufb0 + ((st + 1) & 1) * BUF_SZ, tid);

        const uint32_t bb = bufb0 + (st & 1) * BUF_SZ;
        const uint32_t kb = bb + klane;
        const uint32_t vb = bb + 8704 + vlane;

#pragma unroll
        for (int sub = 0; sub < 2; sub++) {
            // ---- S-MMAs for this 64-col sub (fp16 accum; C frag == P A-frag) ----
            uint32_t sh[2][8][2] = {};   // [m][nb][half]
#pragma unroll
            for (int s = 0; s < 2; s++)
#pragma unroll
                for (int p = 0; p < 4; p++) {
                    uint32_t kf[4];
                    LDSM_T(kf, kb + (16 * s) * 272 + sub * 128 + p * 32);
                    mma16816h(sh[0][2 * p],     qa[0][s], kf[0], kf[1]);
                    mma16816h(sh[0][2 * p + 1], qa[0][s], kf[2], kf[3]);
                    mma16816h(sh[1][2 * p],     qa[1][s], kf[0], kf[1]);
                    mma16816h(sh[1][2 * p + 1], qa[1][s], kf[2], kf[3]);
                }

            // ---- exp2 in place ----
            {
                uint32_t* shp = &sh[0][0][0];
#pragma unroll
                for (int u = 0; u < 32; u++)
                    asm("ex2.approx.f16x2 %0, %0;" : "+r"(shp[u]));
            }

            // ---- O-MMAs (fp16 accum) + rowsum MMA (f32 accum) ----
#pragma unroll
            for (int k2 = 0; k2 < 4; k2++) {
                uint32_t v0[4], v1[4];
                LDSM_N(v0, vb + sub * 128 + k2 * 32);
                LDSM_N(v1, vb + 16 * 272 + sub * 128 + k2 * 32);
#pragma unroll
                for (int m = 0; m < 2; m++) {
                    uint32_t pa[4] = {sh[m][2 * k2][0], sh[m][2 * k2][1],
                                      sh[m][2 * k2 + 1][0], sh[m][2 * k2 + 1][1]};
                    mma16816h(oacc[m][0], pa, v0[0], v0[1]);
                    mma16816h(oacc[m][1], pa, v0[2], v0[3]);
                    mma16816h(oacc[m][2], pa, v1[0], v1[1]);
                    mma16816h(oacc[m][3], pa, v1[2], v1[3]);
                    mma16816(racc[m],    pa, ONES, ONES);
                }
            }
        }
    }

    // LOAD-BEARING: all warps must finish reading the KV ring before the
    // epilogue overlays buffer 0 (final stage reads buffer 0 when nst is odd).
    __syncthreads();

    // partial rowsums (col0 lives in lanes L%4==0: c0 -> row r, c2 -> row r+8)
    if ((L & 3) == 0) {
#pragma unroll
        for (int m = 0; m < 2; m++) {
            int r = 32 * wid + 16 * m + (L >> 2);
            g_prs[sp][hd][i0 + r]     = racc[m][0];
            g_prs[sp][hd][i0 + r + 8] = racc[m][2];
        }
    }

    // stage partial O (already fp16) into smem [d][i], coalesced store
    __half* Osm = (__half*)(araw + QS_SZ);   // 32*136 halves = 8704B
#pragma unroll
    for (int m = 0; m < 2; m++)
#pragma unroll
        for (int nb = 0; nb < 4; nb++) {
            int d_ = 8 * nb + 2 * (L & 3);
            int r = 32 * wid + 16 * m + (L >> 2);
            __half2 h0 = *(__half2*)&oacc[m][nb][0];   // cols d_, d_+1 @ row r
            __half2 h1 = *(__half2*)&oacc[m][nb][1];   // cols d_, d_+1 @ row r+8
            Osm[d_ * 136 + r]           = __low2half(h0);
            Osm[(d_ + 1) * 136 + r]     = __high2half(h0);
            Osm[d_ * 136 + r + 8]       = __low2half(h1);
            Osm[(d_ + 1) * 136 + r + 8] = __high2half(h1);
        }
    __syncthreads();
    __half* Pd = g_po[sp][dir];
#pragma unroll
    for (int u = 0; u < 4; u++) {
        int idx = tid + 128 * u;         // 512 = 32 rows x 16 chunks of 8
        int dd = idx >> 4, c = idx & 15;
        uint4 v = *(uint4*)&Osm[dd * 136 + c * 8];
        *(uint4*)&Pd[(h * 32 + dd) * HW + i0 + c * 8] = v;
    }
}

// ---------------------------------------------------------------------------
// Out projection (HMMA) + FUSED 3-way split-KV combine + bias + residual.
// grid (64 hw-tiles of 64, 2 t), 512 threads — ONE block per hw-tile does all
// 128 output rows; fp16 partials read exactly once (6MB total).
// ---------------------------------------------------------------------------
__global__ void __launch_bounds__(512) outproj_kernel(const float* __restrict__ bA,
                                                      const float* __restrict__ bB,
                                                      float* __restrict__ out) {
    extern __shared__ char oraw[];
    uint32_t wsb = s2u(oraw);                       // W [128][136] halves (34816B)
    uint32_t osb = wsb + 34816;                     // O [128][72] halves  (18432B)
    uint32_t rsb = osb + 18432;                     // res [128][64] f32   (32768B)
    __half* Os = (__half*)(oraw + 34816);
    float* Rs = (float*)(oraw + 34816 + 18432);
    __shared__ float bs[128];
    __shared__ float invs[4][64];
    int t = blockIdx.y;
    const float* bias = t ? bB : bA;
    const float* res = g_xn[t];
    float* Y = out + t * (NC * HW);
    int hw0 = blockIdx.x * 64;
    int tid = threadIdx.x, wid = tid >> 5, L = tid & 31;

#pragma unroll
    for (int u = 0; u < 4; u++) {
        int idx = tid + 512 * u;         // 2048 chunks: W 128 rows x 128 cols
        int row = idx >> 4, c8 = (idx & 15) * 8;
        CP16(wsb + (row * 136 + c8) * 2, g_owh[t] + row * 128 + c8);
    }
#pragma unroll
    for (int u = 0; u < 4; u++) {
        int idx = tid + 512 * u;         // 2048 chunks: res 128x64 f32
        int row = idx >> 4, c4 = (idx & 15) * 4;
        CP16(rsb + (row * 64 + c4) * 4, res + row * HW + hw0 + c4);
    }
    asm volatile("cp.async.commit_group;" ::: "memory");
    if (tid < 128) bs[tid] = bias[tid];

    // inverse combined rowsums: invs[h][c] = 1/(rs0+rs1+rs2)
    if (tid < 256) {
        int h = tid >> 6, c = tid & 63;
        float s = g_prs[0][t * 4 + h][hw0 + c] + g_prs[1][t * 4 + h][hw0 + c]
                + g_prs[2][t * 4 + h][hw0 + c];
        invs[h][c] = 1.f / s;
    }
    __syncthreads();

    // fused combine: O[128][64] = (p0+p1+p2)*inv -> fp16 smem (pitch 72)
    const __half* P0 = g_po[0][t];
    const __half* P1 = g_po[1][t];
    const __half* P2 = g_po[2][t];
#pragma unroll
    for (int u = 0; u < 4; u++) {
        int idx = tid + 512 * u;         // 2048 groups of 4 halves
        int row = idx >> 4, c4 = (idx & 15) * 4;
        int off = row * HW + hw0 + c4;
        uint2 a = *(const uint2*)&P0[off];
        uint2 b = *(const uint2*)&P1[off];
        uint2 d = *(const uint2*)&P2[off];
        __half2 slo = __hadd2(__hadd2(*(__half2*)&a.x, *(__half2*)&b.x), *(__half2*)&d.x);
        __half2 shi = __hadd2(__hadd2(*(__half2*)&a.y, *(__half2*)&b.y), *(__half2*)&d.y);
        float4 iv = *(const float4*)&invs[row >> 5][c4];
        float2 flo = __half22float2(slo);
        float2 fhi = __half22float2(shi);
        __half2 h0 = __floats2half2_rn(flo.x * iv.x, flo.y * iv.y);
        __half2 h1 = __floats2half2_rn(fhi.x * iv.z, fhi.y * iv.w);
        *(uint2*)&Os[row * 72 + c4] = make_uint2(*(uint32_t*)&h0, *(uint32_t*)&h1);
    }
    asm volatile("cp.async.wait_group 0;" ::: "memory");
    __syncthreads();

    int wr = wid & 7, wc = wid >> 3;     // 16 warps: 8 row-groups(16) x 2 col-groups(32)
    uint32_t abase = wsb + ((16 * wr + (L & 15)) * 136 + ((L >> 4) & 1) * 8) * 2;
    uint32_t bbase = osb + (((L & 7) + ((L >> 3) & 1) * 8) * 72 + 32 * wc + ((L >> 4) & 1) * 8) * 2;
    float acc[4][4] = {};
#pragma unroll
    for (int kk = 0; kk < 8; kk++) {
        uint32_t a0[4];
        LDSM_N(a0, abase + (16 * kk) * 2);
        uint32_t bfr[2][4];
#pragma unroll
        for (int nn = 0; nn < 2; nn++)
            LDSM_T(bfr[nn], bbase + (16 * kk * 72 + 16 * nn) * 2);
#pragma unroll
        for (int nn = 0; nn < 2; nn++) {
            mma16816(acc[2 * nn],     a0, bfr[nn][0], bfr[nn][1]);
            mma16816(acc[2 * nn + 1], a0, bfr[nn][2], bfr[nn][3]);
        }
    }
    {
        int rl = 16 * wr + (L >> 2);
#pragma unroll
        for (int nb = 0; nb < 4; nb++) {
            int cl = 32 * wc + 8 * nb + 2 * (L & 3);
            float2 r0 = *(float2*)&Rs[rl * 64 + cl];
            float2 v0;
            v0.x = acc[nb][0] + bs[rl] + r0.x;
            v0.y = acc[nb][1] + bs[rl] + r0.y;
            *(float2*)&Y[rl * HW + hw0 + cl] = v0;
            float2 r1 = *(float2*)&Rs[(rl + 8) * 64 + cl];
            float2 v1;
            v1.x = acc[nb][2] + bs[rl + 8] + r1.x;
            v1.y = acc[nb][3] + bs[rl + 8] + r1.y;
            *(float2*)&Y[(rl + 8) * HW + hw0 + cl] = v1;
        }
    }
}

// ---------------------------------------------------------------------------
extern "C" void kernel_launch(void* const* d_in, const int* in_sizes, int n_in,
                              void* d_out, int out_size) {
    const float* xA    = (const float*)d_in[0];
    const float* xB    = (const float*)d_in[1];
    const float* gnw   = (const float*)d_in[2];
    const float* gnb   = (const float*)d_in[3];
    const float* qkvAw = (const float*)d_in[4];
    const float* outAw = (const float*)d_in[5];
    const float* outAb = (const float*)d_in[6];
    const float* qkvBw = (const float*)d_in[7];
    const float* outBw = (const float*)d_in[8];
    const float* outBb = (const float*)d_in[9];
    float* out = (float*)d_out;

    const int QKV_SMEM  = 34816 + 18432;            // 53248
    const int ATTN_SMEM = QS_SZ + 2 * BUF_SZ;       // 43520
    const int OUT_SMEM  = 34816 + 18432 + 32768;    // 86016
    cudaFuncSetAttribute(qkv_kernel, cudaFuncAttributeMaxDynamicSharedMemorySize, QKV_SMEM);
    cudaFuncSetAttribute(attn_kernel, cudaFuncAttributeMaxDynamicSharedMemorySize, ATTN_SMEM);
    cudaFuncSetAttribute(outproj_kernel, cudaFuncAttributeMaxDynamicSharedMemorySize, OUT_SMEM);

    gnA_kernel<<<dim3(16, 8, 2), 256>>>(xA, xB, qkvAw, qkvBw, outAw, outBw);
    qkv_kernel<<<dim3(64, 3, 2), 256, QKV_SMEM>>>(xA, xB, gnw, gnb);
    attn_kernel<<<dim3(32, 8, 3), 128, ATTN_SMEM>>>();
    outproj_kernel<<<dim3(64, 2), 512, OUT_SMEM>>>(outAb, outBb, out);
}